// round 1
// baseline (speedup 1.0000x reference)
#include <cuda_runtime.h>
#include <math.h>

#define NB 128
#define NP 625
#define NENC 512
#define NA 256
#define NE 256
#define NH 512
#define NV 70
#define NT 70
#define NG 2048
#define NX 768
#define START_TOK 68
#define END_TOK 69

// ---------------- scratch (device globals; no allocations allowed) ----------------
__device__ float g_att1[NB * NP * NA];     // 81.92 MB
__device__ float g_alpha[NB * NP];
__device__ float g_hT[NH * NB];            // transposed h for coalesced GEMM reads
__device__ float g_h[NB * NH];
__device__ float g_c[NB * NH];
__device__ float g_meanT[NENC * NB];
__device__ float g_xT[NX * NB];            // [emb_t ; awe] transposed
__device__ float g_att2[NB * NA];
__device__ float g_gate[NB * NENC];
__device__ float g_gates[NB * NG];
__device__ float g_rowval[NB];
__device__ int   g_rowflat[NB];
__device__ int   g_done[1];

// ---------------- packed f32x2 helpers (full-rate fp32 FMA on sm_103a) ----------------
__device__ __forceinline__ unsigned long long pack2(float lo, float hi) {
    unsigned long long r;
    asm("mov.b64 %0, {%1, %2};" : "=l"(r) : "f"(lo), "f"(hi));
    return r;
}
__device__ __forceinline__ unsigned long long fma2(unsigned long long a, unsigned long long b,
                                                   unsigned long long c) {
    unsigned long long d;
    asm("fma.rn.f32x2 %0, %1, %2, %3;" : "=l"(d) : "l"(a), "l"(b), "l"(c));
    return d;
}
__device__ __forceinline__ float2 unpack2(unsigned long long v) {
    float2 r;
    asm("mov.b64 {%0, %1}, %2;" : "=f"(r.x), "=f"(r.y) : "l"(v));
    return r;
}
__device__ __forceinline__ float sigmoidf_(float x) { return 1.f / (1.f + expf(-x)); }

// ---------------- generic [128 rows] x [K] x [32 cols] GEMM body ----------------
// inT: [K][128] (transposed activations, coalesced). W row-major [K][ldw]. 128 threads.
__device__ __forceinline__ void gemm_rows128(float* ws, const float* __restrict__ inT,
                                             const float* __restrict__ W, int ldw,
                                             int c0, int K, unsigned long long* acc2) {
    const int r = threadIdx.x;
#pragma unroll
    for (int j = 0; j < 16; j++) acc2[j] = 0ULL;
    for (int k0 = 0; k0 < K; k0 += 128) {
        const float4* wrow = (const float4*)(W + (size_t)(k0 + r) * ldw + c0);
        float4* dst = (float4*)(ws + r * 32);
#pragma unroll
        for (int j = 0; j < 8; j++) dst[j] = wrow[j];
        __syncthreads();
#pragma unroll 4
        for (int kk = 0; kk < 128; kk++) {
            float hv = inT[(k0 + kk) * NB + r];
            unsigned long long hv2 = pack2(hv, hv);
            const unsigned long long* wk = (const unsigned long long*)(ws + kk * 32);
#pragma unroll
            for (int j = 0; j < 16; j++) acc2[j] = fma2(hv2, wk[j], acc2[j]);
        }
        __syncthreads();
    }
}

// ---------------- init: mean_enc (transposed), emb0, done=0 ----------------
__global__ void k_init(const float* __restrict__ enc, const float* __restrict__ emb) {
    int b = blockIdx.x, tid = threadIdx.x;  // 512 threads
    const float* eb = enc + (size_t)b * NP * NENC + tid;
    float s0 = 0.f, s1 = 0.f, s2 = 0.f, s3 = 0.f, s4 = 0.f;
#pragma unroll 5
    for (int p = 0; p < NP; p += 5) {
        s0 += eb[(size_t)(p + 0) * NENC];
        s1 += eb[(size_t)(p + 1) * NENC];
        s2 += eb[(size_t)(p + 2) * NENC];
        s3 += eb[(size_t)(p + 3) * NENC];
        s4 += eb[(size_t)(p + 4) * NENC];
    }
    float s = ((s0 + s1) + (s2 + s3)) + s4;
    g_meanT[tid * NB + b] = s / 625.0f;
    if (tid < NE) g_xT[tid * NB + b] = emb[START_TOK * NE + tid];
    if (b == 0 && tid == 0) g_done[0] = 0;
}

// ---------------- att1 = enc @ We + be  ([80000,512] x [512,256]) ----------------
__global__ void k_att1(const float* __restrict__ enc, const float* __restrict__ We,
                       const float* __restrict__ be) {
    __shared__ __align__(16) float ws[128 * 32];
    int bx = blockIdx.x;
    int c0 = (bx & 7) * 32;
    int row = (bx >> 3) * 128 + threadIdx.x;
    int r = threadIdx.x;
    unsigned long long acc2[16];
#pragma unroll
    for (int j = 0; j < 16; j++) acc2[j] = 0ULL;
    const float* erow = enc + (size_t)row * NENC;
    for (int k0 = 0; k0 < NENC; k0 += 128) {
        const float4* wrow = (const float4*)(We + (size_t)(k0 + r) * NA + c0);
        float4* dst = (float4*)(ws + r * 32);
#pragma unroll
        for (int j = 0; j < 8; j++) dst[j] = wrow[j];
        __syncthreads();
#pragma unroll
        for (int kk = 0; kk < 128; kk += 4) {
            float4 ev = *(const float4*)(erow + k0 + kk);
            unsigned long long e0 = pack2(ev.x, ev.x), e1 = pack2(ev.y, ev.y),
                               e2 = pack2(ev.z, ev.z), e3 = pack2(ev.w, ev.w);
            const unsigned long long* w0 = (const unsigned long long*)(ws + (kk + 0) * 32);
            const unsigned long long* w1 = (const unsigned long long*)(ws + (kk + 1) * 32);
            const unsigned long long* w2 = (const unsigned long long*)(ws + (kk + 2) * 32);
            const unsigned long long* w3 = (const unsigned long long*)(ws + (kk + 3) * 32);
#pragma unroll
            for (int j = 0; j < 16; j++) {
                acc2[j] = fma2(e0, w0[j], acc2[j]);
                acc2[j] = fma2(e1, w1[j], acc2[j]);
                acc2[j] = fma2(e2, w2[j], acc2[j]);
                acc2[j] = fma2(e3, w3[j], acc2[j]);
            }
        }
        __syncthreads();
    }
    float vals[32];
#pragma unroll
    for (int j = 0; j < 16; j++) {
        float2 v = unpack2(acc2[j]);
        vals[2 * j] = v.x + be[c0 + 2 * j];
        vals[2 * j + 1] = v.y + be[c0 + 2 * j + 1];
    }
    float* out = g_att1 + (size_t)row * NA + c0;
#pragma unroll
    for (int j = 0; j < 8; j++) {
        float4 f4 = make_float4(vals[4 * j], vals[4 * j + 1], vals[4 * j + 2], vals[4 * j + 3]);
        *(float4*)(out + 4 * j) = f4;
    }
}

// ---------------- h0/c0 = mean_enc @ Wh0/Wc0 + b ----------------
__global__ void k_h0c0(const float* __restrict__ Wh0, const float* __restrict__ bh0,
                       const float* __restrict__ Wc0, const float* __restrict__ bc0) {
    __shared__ __align__(16) float ws[128 * 32];
    unsigned long long acc2[16];
    int bx = blockIdx.x, r = threadIdx.x;
    if (bx < 16) {
        int c0 = bx * 32;
        gemm_rows128(ws, g_meanT, Wh0, NH, c0, NENC, acc2);
#pragma unroll
        for (int j = 0; j < 16; j++) {
            float2 v = unpack2(acc2[j]);
            int c = c0 + 2 * j;
            float a = v.x + bh0[c], bvl = v.y + bh0[c + 1];
            g_h[r * NH + c] = a;     g_h[r * NH + c + 1] = bvl;
            g_hT[c * NB + r] = a;    g_hT[(c + 1) * NB + r] = bvl;
        }
    } else {
        int c0 = (bx - 16) * 32;
        gemm_rows128(ws, g_meanT, Wc0, NH, c0, NENC, acc2);
#pragma unroll
        for (int j = 0; j < 16; j++) {
            float2 v = unpack2(acc2[j]);
            int c = c0 + 2 * j;
            g_c[r * NH + c] = v.x + bc0[c];
            g_c[r * NH + c + 1] = v.y + bc0[c + 1];
        }
    }
}

// ---------------- per-step: att2 = h@Wd+bd ; gate = sigmoid(h@Wb+bb) ; gates = h@Whh + bih + bhh ----------------
__global__ void k_projH(const float* __restrict__ Wd, const float* __restrict__ bd,
                        const float* __restrict__ Wb, const float* __restrict__ bb,
                        const float* __restrict__ Whh, const float* __restrict__ bih,
                        const float* __restrict__ bhh) {
    __shared__ __align__(16) float ws[128 * 32];
    unsigned long long acc2[16];
    int bx = blockIdx.x, r = threadIdx.x;
    if (bx < 8) {
        int c0 = bx * 32;
        gemm_rows128(ws, g_hT, Wd, NA, c0, NH, acc2);
        float* out = g_att2 + r * NA + c0;
#pragma unroll
        for (int j = 0; j < 16; j++) {
            float2 v = unpack2(acc2[j]);
            out[2 * j] = v.x + bd[c0 + 2 * j];
            out[2 * j + 1] = v.y + bd[c0 + 2 * j + 1];
        }
    } else if (bx < 24) {
        int c0 = (bx - 8) * 32;
        gemm_rows128(ws, g_hT, Wb, NENC, c0, NH, acc2);
        float* out = g_gate + r * NENC + c0;
#pragma unroll
        for (int j = 0; j < 16; j++) {
            float2 v = unpack2(acc2[j]);
            out[2 * j] = sigmoidf_(v.x + bb[c0 + 2 * j]);
            out[2 * j + 1] = sigmoidf_(v.y + bb[c0 + 2 * j + 1]);
        }
    } else {
        int c0 = (bx - 24) * 32;
        gemm_rows128(ws, g_hT, Whh, NG, c0, NH, acc2);
        float* out = g_gates + r * NG + c0;
#pragma unroll
        for (int j = 0; j < 16; j++) {
            float2 v = unpack2(acc2[j]);
            int c = c0 + 2 * j;
            out[2 * j] = v.x + bih[c] + bhh[c];
            out[2 * j + 1] = v.y + bih[c + 1] + bhh[c + 1];
        }
    }
}

// ---------------- per-step: e = relu(att1 + att2) . wf ; alpha = softmax(e) ----------------
__global__ void k_epass(const float* __restrict__ wf) {
    int b = blockIdx.x, tid = threadIdx.x, wid = tid >> 5, lane = tid & 31;  // 256 threads
    __shared__ __align__(16) float att2s[NA];
    __shared__ __align__(16) float wfs[NA];
    __shared__ float es[NP];
    __shared__ float red[256];
    if (tid < NA) {
        att2s[tid] = g_att2[b * NA + tid];
        wfs[tid] = wf[tid];
    }
    __syncthreads();
    const float4* base = (const float4*)(g_att1 + (size_t)b * NP * NA);
    float4 a0 = ((const float4*)att2s)[lane], a1 = ((const float4*)att2s)[32 + lane];
    float4 w0 = ((const float4*)wfs)[lane], w1 = ((const float4*)wfs)[32 + lane];
    for (int p0 = wid * 4; p0 < NP; p0 += 32) {
        float4 v[4][2];
#pragma unroll
        for (int u = 0; u < 4; u++) {
            int p = p0 + u;
            if (p < NP) {
                v[u][0] = base[(size_t)p * 64 + lane];
                v[u][1] = base[(size_t)p * 64 + 32 + lane];
            }
        }
#pragma unroll
        for (int u = 0; u < 4; u++) {
            int p = p0 + u;
            if (p < NP) {
                float s = fmaxf(v[u][0].x + a0.x, 0.f) * w0.x + fmaxf(v[u][0].y + a0.y, 0.f) * w0.y +
                          fmaxf(v[u][0].z + a0.z, 0.f) * w0.z + fmaxf(v[u][0].w + a0.w, 0.f) * w0.w +
                          fmaxf(v[u][1].x + a1.x, 0.f) * w1.x + fmaxf(v[u][1].y + a1.y, 0.f) * w1.y +
                          fmaxf(v[u][1].z + a1.z, 0.f) * w1.z + fmaxf(v[u][1].w + a1.w, 0.f) * w1.w;
#pragma unroll
                for (int o = 16; o > 0; o >>= 1) s += __shfl_down_sync(0xffffffffu, s, o);
                if (lane == 0) es[p] = s;
            }
        }
    }
    __syncthreads();
    // softmax over es[0..624]
    float m = -INFINITY;
    for (int i = tid; i < NP; i += 256) m = fmaxf(m, es[i]);
    red[tid] = m;
    __syncthreads();
    for (int s2 = 128; s2 > 0; s2 >>= 1) {
        if (tid < s2) red[tid] = fmaxf(red[tid], red[tid + s2]);
        __syncthreads();
    }
    float M = red[0];
    __syncthreads();
    float sum = 0.f;
    for (int i = tid; i < NP; i += 256) {
        float v2 = expf(es[i] - M);
        es[i] = v2;
        sum += v2;
    }
    red[tid] = sum;
    __syncthreads();
    for (int s2 = 128; s2 > 0; s2 >>= 1) {
        if (tid < s2) red[tid] += red[tid + s2];
        __syncthreads();
    }
    float S = red[0];
    for (int i = tid; i < NP; i += 256) g_alpha[b * NP + i] = es[i] / S;
}

// ---------------- per-step: awe = gate * (alpha @ enc) -> xT[256..768) ----------------
__global__ void k_awe(const float* __restrict__ enc) {
    int b = blockIdx.x, tid = threadIdx.x;  // 512 threads
    int q = tid & 127, pg = tid >> 7;
    __shared__ float alphas[NP];
    __shared__ __align__(16) float4 part[3][128];
    for (int i = tid; i < NP; i += 512) alphas[i] = g_alpha[b * NP + i];
    __syncthreads();
    const float4* eb = (const float4*)(enc + (size_t)b * NP * NENC);
    float4 acc = make_float4(0.f, 0.f, 0.f, 0.f);
    for (int p0 = pg; p0 < NP; p0 += 16) {
        float4 l[4];
        float al[4];
#pragma unroll
        for (int u = 0; u < 4; u++) {
            int p = p0 + 4 * u;
            if (p < NP) {
                l[u] = eb[(size_t)p * 128 + q];
                al[u] = alphas[p];
            }
        }
#pragma unroll
        for (int u = 0; u < 4; u++) {
            int p = p0 + 4 * u;
            if (p < NP) {
                acc.x += al[u] * l[u].x;
                acc.y += al[u] * l[u].y;
                acc.z += al[u] * l[u].z;
                acc.w += al[u] * l[u].w;
            }
        }
    }
    if (pg > 0) part[pg - 1][q] = acc;
    __syncthreads();
    if (pg == 0) {
        float4 a1 = part[0][q], a2 = part[1][q], a3 = part[2][q];
        acc.x += a1.x + a2.x + a3.x;
        acc.y += a1.y + a2.y + a3.y;
        acc.z += a1.z + a2.z + a3.z;
        acc.w += a1.w + a2.w + a3.w;
        float4 g = ((const float4*)(g_gate + b * NENC))[q];
        int k = NE + q * 4;
        g_xT[(k + 0) * NB + b] = acc.x * g.x;
        g_xT[(k + 1) * NB + b] = acc.y * g.y;
        g_xT[(k + 2) * NB + b] = acc.z * g.z;
        g_xT[(k + 3) * NB + b] = acc.w * g.w;
    }
}

// ---------------- per-step: gates += x @ Wih ----------------
__global__ void k_wih(const float* __restrict__ Wih) {
    __shared__ __align__(16) float ws[128 * 32];
    unsigned long long acc2[16];
    int c0 = blockIdx.x * 32, r = threadIdx.x;
    gemm_rows128(ws, g_xT, Wih, NG, c0, NX, acc2);
    float* out = g_gates + r * NG + c0;
#pragma unroll
    for (int j = 0; j < 16; j++) {
        float2 v = unpack2(acc2[j]);
        out[2 * j] += v.x;
        out[2 * j + 1] += v.y;
    }
}

// ---------------- per-step: LSTM pointwise ----------------
__global__ void k_lstm() {
    int b = blockIdx.x, j = threadIdx.x;  // 512 threads
    const float* gr = g_gates + b * NG;
    float i_ = gr[j], f_ = gr[j + 512], gg = gr[j + 1024], o_ = gr[j + 1536];
    float c = g_c[b * NH + j];
    float si = sigmoidf_(i_), sf = sigmoidf_(f_), so = sigmoidf_(o_);
    float tg = tanhf(gg);
    float cn = sf * c + si * tg;
    float hn = so * tanhf(cn);
    g_c[b * NH + j] = cn;
    g_h[b * NH + j] = hn;
    g_hT[j * NB + b] = hn;
}

// ---------------- per-step: preds, output write, per-row argmax, emb feedback ----------------
__global__ void k_preds(const float* __restrict__ Wfc, const float* __restrict__ bfc,
                        const float* __restrict__ emb, float* __restrict__ out, int t) {
    int b = blockIdx.x, tid = threadIdx.x;  // 128 threads
    __shared__ float hs[NH];
    __shared__ float rv[128];
    __shared__ int ri[128];
    __shared__ int widx;
#pragma unroll
    for (int i = 0; i < 4; i++) hs[tid + 128 * i] = g_h[b * NH + tid + 128 * i];
    __syncthreads();
    float val = -INFINITY;
    if (tid < NV) {
        float acc = bfc[tid];
#pragma unroll 8
        for (int k = 0; k < NH; k++) acc = fmaf(hs[k], Wfc[k * NV + tid], acc);
        val = acc;
        int done = g_done[0];
        out[(size_t)b * NT * NV + (size_t)t * NV + tid] = done ? 0.f : acc;
    }
    rv[tid] = val;
    ri[tid] = tid;
    __syncthreads();
    for (int s = 64; s > 0; s >>= 1) {
        if (tid < s) {
            float ov = rv[tid + s];
            int oi = ri[tid + s];
            if (ov > rv[tid] || (ov == rv[tid] && oi < ri[tid])) {
                rv[tid] = ov;
                ri[tid] = oi;
            }
        }
        __syncthreads();
    }
    if (tid == 0) {
        g_rowval[b] = rv[0];
        g_rowflat[b] = b * NV + ri[0];
        widx = ri[0];
    }
    __syncthreads();
    int w = widx;
    g_xT[tid * NB + b] = emb[w * NE + tid];
    g_xT[(tid + 128) * NB + b] = emb[w * NE + tid + 128];
}

// ---------------- per-step: flat argmax over [B,V] -> done flag ----------------
__global__ void k_done() {
    int tid = threadIdx.x;  // 128 threads
    __shared__ float rv[128];
    __shared__ int rf[128];
    rv[tid] = g_rowval[tid];
    rf[tid] = g_rowflat[tid];
    __syncthreads();
    for (int s = 64; s > 0; s >>= 1) {
        if (tid < s) {
            float ov = rv[tid + s];
            int of = rf[tid + s];
            if (ov > rv[tid] || (ov == rv[tid] && of < rf[tid])) {
                rv[tid] = ov;
                rf[tid] = of;
            }
        }
        __syncthreads();
    }
    if (tid == 0 && rf[0] == END_TOK) g_done[0] = 1;
}

extern "C" void kernel_launch(void* const* d_in, const int* in_sizes, int n_in,
                              void* d_out, int out_size) {
    (void)in_sizes; (void)n_in; (void)out_size;
    const float* enc = (const float*)d_in[0];
    const float* emb = (const float*)d_in[1];
    const float* We  = (const float*)d_in[2];
    const float* be  = (const float*)d_in[3];
    const float* Wd  = (const float*)d_in[4];
    const float* bd  = (const float*)d_in[5];
    const float* wf  = (const float*)d_in[6];
    const float* Wh0 = (const float*)d_in[8];
    const float* bh0 = (const float*)d_in[9];
    const float* Wc0 = (const float*)d_in[10];
    const float* bc0 = (const float*)d_in[11];
    const float* Wb  = (const float*)d_in[12];
    const float* bb  = (const float*)d_in[13];
    const float* Wih = (const float*)d_in[14];
    const float* Whh = (const float*)d_in[15];
    const float* bih = (const float*)d_in[16];
    const float* bhh = (const float*)d_in[17];
    const float* Wfc = (const float*)d_in[18];
    const float* bfc = (const float*)d_in[19];
    float* out = (float*)d_out;

    k_init<<<NB, 512>>>(enc, emb);
    k_att1<<<5000, 128>>>(enc, We, be);
    k_h0c0<<<32, 128>>>(Wh0, bh0, Wc0, bc0);
    for (int t = 0; t < NT; t++) {
        k_projH<<<88, 128>>>(Wd, bd, Wb, bb, Whh, bih, bhh);
        k_epass<<<NB, 256>>>(wf);
        k_awe<<<NB, 512>>>(enc);
        k_wih<<<64, 128>>>(Wih);
        k_lstm<<<NB, 512>>>();
        k_preds<<<NB, 128>>>(Wfc, bfc, emb, out, t);
        k_done<<<1, 128>>>();
    }
}

// round 2
// speedup vs baseline: 2.4880x; 2.4880x over previous
#include <cuda_runtime.h>
#include <math.h>

#define NB 128
#define NP 625
#define NENC 512
#define NA 256
#define NE 256
#define NH 512
#define NV 70
#define NT 70
#define NG 2048
#define NX 768
#define KC 64
#define START_TOK 68
#define END_TOK 69

// ---------------- scratch ----------------
__device__ float g_att1[NB * NP * NA];   // 81.92MB
__device__ float g_h[NB * NH];
__device__ float g_c[NB * NH];
__device__ float g_mean[NB * NENC];
__device__ float g_x[NB * NX];           // [emb_t | gated awe] row-major
__device__ float g_att2[NB * NA];
__device__ float g_gate[NB * NENC];
__device__ float g_gates[NB * NG];       // h@Whh + bih + bhh
__device__ float g_gp0[NB * NG];         // x[:,0:384] @ Wih[0:384]
__device__ float g_gp1[NB * NG];         // x[:,384:768] @ Wih[384:768]
__device__ float g_WfcT[NV * NH];
__device__ float g_rowval[NB];
__device__ int   g_rowflat[NB];
__device__ int   g_done[1];

// ---------------- f32x2 helpers ----------------
__device__ __forceinline__ unsigned long long fma2(unsigned long long a, unsigned long long b,
                                                   unsigned long long c) {
    unsigned long long d;
    asm("fma.rn.f32x2 %0, %1, %2, %3;" : "=l"(d) : "l"(a), "l"(b), "l"(c));
    return d;
}
__device__ __forceinline__ float2 unpack2(unsigned long long v) {
    float2 r;
    asm("mov.b64 {%0, %1}, %2;" : "=f"(r.x), "=f"(r.y) : "l"(v));
    return r;
}
__device__ __forceinline__ float sigmoidf_(float x) { return 1.f / (1.f + expf(-x)); }

// ---------------- core GEMM tile: C[128, c0:c0+32] = A[128,K] @ W[K, ldw] ----------------
// 256 threads. A row-major (lda), W row-major (ldw). K % 64 == 0.
// acc[8]: u64 f32x2 pairs over M. Thread covers rows m8..m8+7, cols c0+n2, c0+n2+1.
__device__ __forceinline__ void gemm128x32(const float* __restrict__ A, int lda,
                                           const float* __restrict__ W, int ldw, int c0, int K,
                                           unsigned long long acc[8], float* As, float2* Bs) {
    const int tid = threadIdx.x;
    const int m8 = (tid >> 4) * 8;
    const int n2 = (tid & 15) * 2;
    const int la_m = tid & 127, la_k = (tid >> 7) * 32;
    const int lb_n = tid & 31, lb_k = tid >> 5;
#pragma unroll
    for (int j = 0; j < 8; j++) acc[j] = 0ULL;
    float4 pa[8];
    float pb[8];
    const float* Arow = A + (size_t)la_m * lda + la_k;
    const float* Wcol = W + (size_t)lb_k * ldw + c0 + lb_n;
#pragma unroll
    for (int j = 0; j < 8; j++) pa[j] = *(const float4*)(Arow + 4 * j);
#pragma unroll
    for (int j = 0; j < 8; j++) pb[j] = Wcol[(size_t)(8 * j) * ldw];
    const int nc = K / KC;
    for (int ch = 0;;) {
#pragma unroll
        for (int j = 0; j < 8; j++) {
            float4 v = pa[j];
            int kk = la_k + 4 * j;
            As[(kk + 0) * 128 + la_m] = v.x;
            As[(kk + 1) * 128 + la_m] = v.y;
            As[(kk + 2) * 128 + la_m] = v.z;
            As[(kk + 3) * 128 + la_m] = v.w;
        }
#pragma unroll
        for (int j = 0; j < 8; j++) Bs[(lb_k + 8 * j) * 32 + lb_n] = make_float2(pb[j], pb[j]);
        __syncthreads();
        if (ch + 1 < nc) {
            const float* Ar2 = Arow + (ch + 1) * KC;
            const float* Wc2 = Wcol + (size_t)((ch + 1) * KC) * ldw;
#pragma unroll
            for (int j = 0; j < 8; j++) pa[j] = *(const float4*)(Ar2 + 4 * j);
#pragma unroll
            for (int j = 0; j < 8; j++) pb[j] = Wc2[(size_t)(8 * j) * ldw];
        }
        const unsigned long long* As2 = (const unsigned long long*)As;
        const unsigned long long* Bs2 = (const unsigned long long*)Bs;
#pragma unroll 8
        for (int k = 0; k < KC; k++) {
            unsigned long long b0 = Bs2[k * 32 + n2], b1 = Bs2[k * 32 + n2 + 1];
            const unsigned long long* ap = &As2[k * 64 + (m8 >> 1)];
            unsigned long long a0 = ap[0], a1 = ap[1], a2 = ap[2], a3 = ap[3];
            acc[0] = fma2(a0, b0, acc[0]);
            acc[1] = fma2(a0, b1, acc[1]);
            acc[2] = fma2(a1, b0, acc[2]);
            acc[3] = fma2(a1, b1, acc[3]);
            acc[4] = fma2(a2, b0, acc[4]);
            acc[5] = fma2(a2, b1, acc[5]);
            acc[6] = fma2(a3, b0, acc[6]);
            acc[7] = fma2(a3, b1, acc[7]);
        }
        __syncthreads();
        if (++ch == nc) break;
    }
}

// ---------------- init: mean_enc, emb0, WfcT, flags ----------------
__global__ void k_init(const float* __restrict__ enc, const float* __restrict__ emb,
                       const float* __restrict__ Wfc) {
    int bx = blockIdx.x, tid = threadIdx.x;  // 512 threads
    if (bx < NB) {
        const float* eb = enc + (size_t)bx * NP * NENC + tid;
        float s0 = 0.f, s1 = 0.f, s2 = 0.f, s3 = 0.f, s4 = 0.f;
#pragma unroll 5
        for (int p = 0; p < NP; p += 5) {
            s0 += eb[(size_t)(p + 0) * NENC];
            s1 += eb[(size_t)(p + 1) * NENC];
            s2 += eb[(size_t)(p + 2) * NENC];
            s3 += eb[(size_t)(p + 3) * NENC];
            s4 += eb[(size_t)(p + 4) * NENC];
        }
        g_mean[bx * NENC + tid] = (((s0 + s1) + (s2 + s3)) + s4) / 625.0f;
        if (tid < NE) g_x[bx * NX + tid] = emb[START_TOK * NE + tid];
        if (tid == 0) {
            g_rowval[bx] = -INFINITY;
            g_rowflat[bx] = 0;
        }
        if (bx == 0 && tid == 0) g_done[0] = 0;
    } else {
        int col = bx - NB;
        g_WfcT[col * NH + tid] = Wfc[tid * NV + col];
    }
}

// ---------------- h0/c0 ----------------
__global__ __launch_bounds__(256) void k_h0c0(const float* __restrict__ Wh0,
                                              const float* __restrict__ bh0,
                                              const float* __restrict__ Wc0,
                                              const float* __restrict__ bc0) {
    __shared__ __align__(16) float As[KC * 128];
    __shared__ __align__(16) float2 Bs[KC * 32];
    int bx = blockIdx.x, tid = threadIdx.x;
    unsigned long long acc[8];
    const float* W = (bx < 16) ? Wh0 : Wc0;
    const float* bias = (bx < 16) ? bh0 : bc0;
    float* out = (bx < 16) ? g_h : g_c;
    int c0 = (bx & 15) * 32;
    gemm128x32(g_mean, NENC, W, NH, c0, NENC, acc, As, Bs);
    int m8 = (tid >> 4) * 8, n2 = (tid & 15) * 2;
#pragma unroll
    for (int mp = 0; mp < 4; mp++)
#pragma unroll
        for (int nn = 0; nn < 2; nn++) {
            float2 v = unpack2(acc[mp * 2 + nn]);
            int r = m8 + 2 * mp, c = c0 + n2 + nn;
            out[r * NH + c] = v.x + bias[c];
            out[(r + 1) * NH + c] = v.y + bias[c];
        }
}

// ---------------- att1 = enc @ We + be ----------------
__global__ __launch_bounds__(256) void k_att1(const float* __restrict__ enc,
                                              const float* __restrict__ We,
                                              const float* __restrict__ be) {
    __shared__ __align__(16) float As[KC * 128];
    __shared__ __align__(16) float2 Bs[KC * 32];
    int bx = blockIdx.x, tid = threadIdx.x;
    int mt = bx >> 3, c0 = (bx & 7) * 32;
    unsigned long long acc[8];
    gemm128x32(enc + (size_t)mt * 128 * NENC, NENC, We, NA, c0, NENC, acc, As, Bs);
    int m8 = (tid >> 4) * 8, n2 = (tid & 15) * 2;
    float* out = g_att1 + (size_t)mt * 128 * NA;
#pragma unroll
    for (int mp = 0; mp < 4; mp++)
#pragma unroll
        for (int nn = 0; nn < 2; nn++) {
            float2 v = unpack2(acc[mp * 2 + nn]);
            int r = m8 + 2 * mp, c = c0 + n2 + nn;
            out[(size_t)r * NA + c] = v.x + be[c];
            out[(size_t)(r + 1) * NA + c] = v.y + be[c];
        }
}

// ---------------- K1: att2 / gate / gates(h@Whh) GEMMs + done-flag update ----------------
__global__ __launch_bounds__(256) void k_projH(const float* __restrict__ Wd,
                                               const float* __restrict__ bd,
                                               const float* __restrict__ Wb,
                                               const float* __restrict__ bb,
                                               const float* __restrict__ Whh,
                                               const float* __restrict__ bih,
                                               const float* __restrict__ bhh) {
    __shared__ __align__(16) float As[KC * 128];
    __shared__ __align__(16) float2 Bs[KC * 32];
    int bx = blockIdx.x, tid = threadIdx.x;
    if (bx == 0) {  // update done flag from previous step's row argmaxes
        float* dv = As;
        int* dfi = (int*)(As + 192);
        if (tid < 128) {
            dv[tid] = g_rowval[tid];
            dfi[tid] = g_rowflat[tid];
        }
        __syncthreads();
        for (int s = 64; s > 0; s >>= 1) {
            if (tid < s) {
                float ov = dv[tid + s];
                int of = dfi[tid + s];
                if (ov > dv[tid] || (ov == dv[tid] && of < dfi[tid])) {
                    dv[tid] = ov;
                    dfi[tid] = of;
                }
            }
            __syncthreads();
        }
        if (tid == 0 && dfi[0] == END_TOK) g_done[0] = 1;
        __syncthreads();
    }
    unsigned long long acc[8];
    const float* W;
    int ldw, c0, seg;
    if (bx < 8) {
        W = Wd; ldw = NA; c0 = bx * 32; seg = 0;
    } else if (bx < 24) {
        W = Wb; ldw = NENC; c0 = (bx - 8) * 32; seg = 1;
    } else {
        W = Whh; ldw = NG; c0 = (bx - 24) * 32; seg = 2;
    }
    gemm128x32(g_h, NH, W, ldw, c0, NH, acc, As, Bs);
    int m8 = (tid >> 4) * 8, n2 = (tid & 15) * 2;
#pragma unroll
    for (int mp = 0; mp < 4; mp++)
#pragma unroll
        for (int nn = 0; nn < 2; nn++) {
            float2 v = unpack2(acc[mp * 2 + nn]);
            int r = m8 + 2 * mp, c = c0 + n2 + nn;
            if (seg == 0) {
                g_att2[r * NA + c] = v.x + bd[c];
                g_att2[(r + 1) * NA + c] = v.y + bd[c];
            } else if (seg == 1) {
                g_gate[r * NENC + c] = sigmoidf_(v.x + bb[c]);
                g_gate[(r + 1) * NENC + c] = sigmoidf_(v.y + bb[c]);
            } else {
                float lb = bih[c] + bhh[c];
                g_gates[r * NG + c] = v.x + lb;
                g_gates[(r + 1) * NG + c] = v.y + lb;
            }
        }
}

// ---------------- K2: fused e-pass + softmax + awe + gating ----------------
__global__ __launch_bounds__(512) void k_att(const float* __restrict__ enc,
                                             const float* __restrict__ wf) {
    int b = blockIdx.x, tid = threadIdx.x, wid = tid >> 5, lane = tid & 31;
    __shared__ __align__(16) float att2s[NA];
    __shared__ __align__(16) float wfs[NA];
    __shared__ float es[NP];
    __shared__ float red[512];
    __shared__ __align__(16) float4 part[3][128];
    if (tid < NA) {
        att2s[tid] = g_att2[b * NA + tid];
        wfs[tid] = wf[tid];
    }
    __syncthreads();
    const float4* base = (const float4*)(g_att1 + (size_t)b * NP * NA);
    float4 a0 = ((const float4*)att2s)[lane], a1 = ((const float4*)att2s)[32 + lane];
    float4 w0 = ((const float4*)wfs)[lane], w1 = ((const float4*)wfs)[32 + lane];
    for (int p0 = wid * 4; p0 < NP; p0 += 64) {
        float4 v[4][2];
#pragma unroll
        for (int u = 0; u < 4; u++) {
            int p = p0 + u;
            if (p < NP) {
                v[u][0] = base[(size_t)p * 64 + lane];
                v[u][1] = base[(size_t)p * 64 + 32 + lane];
            }
        }
#pragma unroll
        for (int u = 0; u < 4; u++) {
            int p = p0 + u;
            if (p < NP) {
                float s = fmaxf(v[u][0].x + a0.x, 0.f) * w0.x + fmaxf(v[u][0].y + a0.y, 0.f) * w0.y +
                          fmaxf(v[u][0].z + a0.z, 0.f) * w0.z + fmaxf(v[u][0].w + a0.w, 0.f) * w0.w +
                          fmaxf(v[u][1].x + a1.x, 0.f) * w1.x + fmaxf(v[u][1].y + a1.y, 0.f) * w1.y +
                          fmaxf(v[u][1].z + a1.z, 0.f) * w1.z + fmaxf(v[u][1].w + a1.w, 0.f) * w1.w;
#pragma unroll
                for (int o = 16; o > 0; o >>= 1) s += __shfl_down_sync(0xffffffffu, s, o);
                if (lane == 0) es[p] = s;
            }
        }
    }
    __syncthreads();
    // softmax over es
    float m = -INFINITY;
    for (int i = tid; i < NP; i += 512) m = fmaxf(m, es[i]);
    red[tid] = m;
    __syncthreads();
    for (int s2 = 256; s2 > 0; s2 >>= 1) {
        if (tid < s2) red[tid] = fmaxf(red[tid], red[tid + s2]);
        __syncthreads();
    }
    float M = red[0];
    __syncthreads();
    float sum = 0.f;
    for (int i = tid; i < NP; i += 512) {
        float v = expf(es[i] - M);
        es[i] = v;
        sum += v;
    }
    red[tid] = sum;
    __syncthreads();
    for (int s2 = 256; s2 > 0; s2 >>= 1) {
        if (tid < s2) red[tid] += red[tid + s2];
        __syncthreads();
    }
    float inv = 1.f / red[0];
    __syncthreads();
    for (int i = tid; i < NP; i += 512) es[i] *= inv;
    __syncthreads();
    // awe = alpha @ enc
    int q = tid & 127, pg = tid >> 7;
    const float4* eb = (const float4*)(enc + (size_t)b * NP * NENC);
    float4 acc = make_float4(0.f, 0.f, 0.f, 0.f);
#pragma unroll 4
    for (int p = pg; p < NP; p += 4) {
        float al = es[p];
        float4 l = eb[(size_t)p * 128 + q];
        acc.x += al * l.x;
        acc.y += al * l.y;
        acc.z += al * l.z;
        acc.w += al * l.w;
    }
    if (pg > 0) part[pg - 1][q] = acc;
    __syncthreads();
    if (pg == 0) {
        float4 p1 = part[0][q], p2 = part[1][q], p3 = part[2][q];
        acc.x += p1.x + p2.x + p3.x;
        acc.y += p1.y + p2.y + p3.y;
        acc.z += p1.z + p2.z + p3.z;
        acc.w += p1.w + p2.w + p3.w;
        float4 g = ((const float4*)(g_gate + b * NENC))[q];
        float4 o = make_float4(acc.x * g.x, acc.y * g.y, acc.z * g.z, acc.w * g.w);
        *(float4*)(g_x + b * NX + NE + 4 * q) = o;
    }
}

// ---------------- K3: x @ Wih, deterministic K-split into 2 partials ----------------
__global__ __launch_bounds__(256) void k_wih(const float* __restrict__ Wih) {
    __shared__ __align__(16) float As[KC * 128];
    __shared__ __align__(16) float2 Bs[KC * 32];
    int bx = blockIdx.x, tid = threadIdx.x;
    int seg = bx >> 6;             // 0 or 1
    int c0 = (bx & 63) * 32;
    unsigned long long acc[8];
    gemm128x32(g_x + seg * 384, NX, Wih + (size_t)(seg * 384) * NG, NG, c0, 384, acc, As, Bs);
    float* out = seg ? g_gp1 : g_gp0;
    int m8 = (tid >> 4) * 8, n2 = (tid & 15) * 2;
#pragma unroll
    for (int mp = 0; mp < 4; mp++)
#pragma unroll
        for (int nn = 0; nn < 2; nn++) {
            float2 v = unpack2(acc[mp * 2 + nn]);
            int r = m8 + 2 * mp, c = c0 + n2 + nn;
            out[r * NG + c] = v.x;
            out[(r + 1) * NG + c] = v.y;
        }
}

// ---------------- K4: LSTM pointwise + preds + argmax + emb feedback ----------------
__global__ __launch_bounds__(512) void k_step(const float* __restrict__ bfc,
                                              const float* __restrict__ emb,
                                              float* __restrict__ out, int t) {
    int b = blockIdx.x, tid = threadIdx.x, wid = tid >> 5, lane = tid & 31;
    __shared__ __align__(16) float hs[NH];
    __shared__ float pv[128];
    __shared__ int pi_[128];
    __shared__ int widx;
    {
        int j = tid;
        const float* ga = g_gates + b * NG;
        const float* p0 = g_gp0 + b * NG;
        const float* p1 = g_gp1 + b * NG;
        float iv = ga[j] + p0[j] + p1[j];
        float fv = ga[j + 512] + p0[j + 512] + p1[j + 512];
        float gv = ga[j + 1024] + p0[j + 1024] + p1[j + 1024];
        float ov = ga[j + 1536] + p0[j + 1536] + p1[j + 1536];
        float c = g_c[b * NH + j];
        float cn = sigmoidf_(fv) * c + sigmoidf_(iv) * tanhf(gv);
        float hn = sigmoidf_(ov) * tanhf(cn);
        g_c[b * NH + j] = cn;
        g_h[b * NH + j] = hn;
        hs[j] = hn;
    }
    if (tid < 128) {
        pv[tid] = -INFINITY;
        pi_[tid] = tid;
    }
    __syncthreads();
    int done = g_done[0];
    const float4* hs4 = (const float4*)hs;
    for (int col = wid; col < NV; col += 16) {
        const float4* wr = (const float4*)(g_WfcT + col * NH);
        float s = 0.f;
#pragma unroll
        for (int i = 0; i < 4; i++) {
            float4 h4 = hs4[lane + 32 * i];
            float4 w4 = wr[lane + 32 * i];
            s += h4.x * w4.x + h4.y * w4.y + h4.z * w4.z + h4.w * w4.w;
        }
#pragma unroll
        for (int o = 16; o > 0; o >>= 1) s += __shfl_down_sync(0xffffffffu, s, o);
        if (lane == 0) {
            s += bfc[col];
            out[(size_t)b * NT * NV + (size_t)t * NV + col] = done ? 0.f : s;
            pv[col] = s;
            pi_[col] = col;
        }
    }
    __syncthreads();
    for (int s2 = 64; s2 > 0; s2 >>= 1) {
        if (tid < s2) {
            float ov = pv[tid + s2];
            int oi = pi_[tid + s2];
            if (ov > pv[tid] || (ov == pv[tid] && oi < pi_[tid])) {
                pv[tid] = ov;
                pi_[tid] = oi;
            }
        }
        __syncthreads();
    }
    if (tid == 0) {
        g_rowval[b] = pv[0];
        g_rowflat[b] = b * NV + pi_[0];
        widx = pi_[0];
    }
    __syncthreads();
    if (tid < NE) g_x[b * NX + tid] = emb[widx * NE + tid];
}

extern "C" void kernel_launch(void* const* d_in, const int* in_sizes, int n_in,
                              void* d_out, int out_size) {
    (void)in_sizes; (void)n_in; (void)out_size;
    const float* enc = (const float*)d_in[0];
    const float* emb = (const float*)d_in[1];
    const float* We  = (const float*)d_in[2];
    const float* be  = (const float*)d_in[3];
    const float* Wd  = (const float*)d_in[4];
    const float* bd  = (const float*)d_in[5];
    const float* wf  = (const float*)d_in[6];
    const float* Wh0 = (const float*)d_in[8];
    const float* bh0 = (const float*)d_in[9];
    const float* Wc0 = (const float*)d_in[10];
    const float* bc0 = (const float*)d_in[11];
    const float* Wb  = (const float*)d_in[12];
    const float* bb  = (const float*)d_in[13];
    const float* Wih = (const float*)d_in[14];
    const float* Whh = (const float*)d_in[15];
    const float* bih = (const float*)d_in[16];
    const float* bhh = (const float*)d_in[17];
    const float* Wfc = (const float*)d_in[18];
    const float* bfc = (const float*)d_in[19];
    float* out = (float*)d_out;

    k_init<<<NB + NV, 512>>>(enc, emb, Wfc);
    k_att1<<<5000, 256>>>(enc, We, be);
    k_h0c0<<<32, 256>>>(Wh0, bh0, Wc0, bc0);
    for (int t = 0; t < NT; t++) {
        k_projH<<<88, 256>>>(Wd, bd, Wb, bb, Whh, bih, bhh);
        k_att<<<NB, 512>>>(enc, wf);
        k_wih<<<128, 256>>>(Wih);
        k_step<<<NB, 512>>>(bfc, emb, out, t);
    }
}